// round 13
// baseline (speedup 1.0000x reference)
#include <cuda_runtime.h>
#include <cuda_bf16.h>
#include <math.h>

#define BQ 2
#define S_LEN 2048
#define HK 16
#define HV 32
#define DK 128
#define DV 128
#define QKV 8192
#define NROWS (BQ * S_LEN)
#define TB 16   // tokens per smem staging batch (rec); 4 groups of 4
#define GB (TB / 4)

typedef unsigned long long ull;

// ---------------- scratch (device globals; no runtime allocation) ----------------
__device__ float g_qn[(size_t)NROWS * HK * DK];    // l2norm(q) * scale
__device__ float g_kn[(size_t)NROWS * HK * DK];    // l2norm(k)
__device__ float g_v [(size_t)NROWS * HV * DV];
__device__ float g_gate[(size_t)NROWS * HV * 2];   // float2 per (row,h): eg, beta
// per (b, token-group, hk): 12 cross scalars in 3 float4s
// [kk21,kk31,kk32,kk41][kk42,kk43,qk11,qk21][qk22,qk31,qk32,qk33]
__device__ float4 g_cross4[(size_t)BQ * (S_LEN / 4) * HK * 3];

// ---------------- packed f32x2 helpers ----------------
__device__ __forceinline__ ull pack2(float lo, float hi) {
    ull r;
    asm("mov.b64 %0, {%1,%2};" : "=l"(r) : "f"(lo), "f"(hi));
    return r;
}
__device__ __forceinline__ float2 unpack2(ull v) {
    float2 r;
    asm("mov.b64 {%0,%1}, %2;" : "=f"(r.x), "=f"(r.y) : "l"(v));
    return r;
}
__device__ __forceinline__ float sum2(ull v) {
    float2 r = unpack2(v);
    return r.x + r.y;
}
#define FMA2(d, a, b, c) asm("fma.rn.f32x2 %0, %1, %2, %3;" : "=l"(d) : "l"(a), "l"(b), "l"(c))
#define MUL2(d, a, b)    asm("mul.rn.f32x2 %0, %1, %2;"     : "=l"(d) : "l"(a), "l"(b))
#define ADD2(d, a, b)    asm("add.rn.f32x2 %0, %1, %2;"     : "=l"(d) : "l"(a), "l"(b))

union F4U { float4 f; ull u[2]; };

// ---------------- cp.async helpers ----------------
__device__ __forceinline__ void cpa16(void* smem, const void* gmem) {
    unsigned s = (unsigned)__cvta_generic_to_shared(smem);
    asm volatile("cp.async.cg.shared.global [%0], [%1], 16;" :: "r"(s), "l"(gmem));
}
__device__ __forceinline__ void cpa8(void* smem, const void* gmem) {
    unsigned s = (unsigned)__cvta_generic_to_shared(smem);
    asm volatile("cp.async.ca.shared.global [%0], [%1], 8;" :: "r"(s), "l"(gmem));
}
__device__ __forceinline__ void cpa_commit() {
    asm volatile("cp.async.commit_group;" ::: "memory");
}
__device__ __forceinline__ void cpa_wait0() {
    asm volatile("cp.async.wait_group 0;" ::: "memory");
}

// ---------------- kernel 1: register sliding-window conv + silu + l2norm ----------------
__global__ __launch_bounds__(256) void prep_kernel(
    const float* __restrict__ x,      // [NROWS, QKV]
    const float* __restrict__ w)      // [QKV, 4]
{
    const int gw   = (blockIdx.x * 256 + threadIdx.x) >> 5;
    const int lane = threadIdx.x & 31;
    const int strip = gw & 127;
    const int hb    = (gw >> 7) & 63;
    const int b     = gw >> 13;
    const int t0    = strip * 16;
    const int ch    = hb * 128 + lane * 4;

    const float* xp = x + (size_t)(b * S_LEN + t0) * QKV + ch;

    const float4* w4 = (const float4*)w;
    const float4 wv0 = __ldg(w4 + ch + 0);
    const float4 wv1 = __ldg(w4 + ch + 1);
    const float4 wv2 = __ldg(w4 + ch + 2);
    const float4 wv3 = __ldg(w4 + ch + 3);

    float4 h0 = make_float4(0.f, 0.f, 0.f, 0.f);
    float4 h1 = h0, h2 = h0;
    if (t0 >= 3) {
        h0 = *reinterpret_cast<const float4*>(xp - 3 * QKV);
        h1 = *reinterpret_cast<const float4*>(xp - 2 * QKV);
        h2 = *reinterpret_cast<const float4*>(xp - 1 * QKV);
    }

    const float qscale = 0.08838834764831845f;

#define CONV_STEP(a, T) do {                                                        \
    const float4 xc = *reinterpret_cast<const float4*>(xp + (size_t)(T) * QKV);    \
    a.x = fmaf(h0.x, wv0.x, fmaf(h1.x, wv0.y, fmaf(h2.x, wv0.z, xc.x * wv0.w)));   \
    a.y = fmaf(h0.y, wv1.x, fmaf(h1.y, wv1.y, fmaf(h2.y, wv1.z, xc.y * wv1.w)));   \
    a.z = fmaf(h0.z, wv2.x, fmaf(h1.z, wv2.y, fmaf(h2.z, wv2.z, xc.z * wv2.w)));   \
    a.w = fmaf(h0.w, wv3.x, fmaf(h1.w, wv3.y, fmaf(h2.w, wv3.z, xc.w * wv3.w)));   \
    a.x = a.x / (1.f + __expf(-a.x));                                              \
    a.y = a.y / (1.f + __expf(-a.y));                                              \
    a.z = a.z / (1.f + __expf(-a.z));                                              \
    a.w = a.w / (1.f + __expf(-a.w));                                              \
    h0 = h1; h1 = h2; h2 = xc;                                                     \
} while (0)

    if (hb < 32) {
        const bool isq = hb < 16;
        const int head = isq ? hb : hb - 16;
        float* dbase = (isq ? g_qn : g_kn)
                     + ((size_t)(b * S_LEN + t0) * HK + head) * DK + lane * 4;
        const float sc = isq ? qscale : 1.f;
#pragma unroll
        for (int t = 0; t < 16; t++) {
            float4 a;
            CONV_STEP(a, t);
            float ss = a.x * a.x + a.y * a.y + a.z * a.z + a.w * a.w;
#pragma unroll
            for (int o = 16; o > 0; o >>= 1)
                ss += __shfl_xor_sync(0xffffffffu, ss, o);
            const float mul = rsqrtf(ss + 1e-6f) * sc;
            a.x *= mul; a.y *= mul; a.z *= mul; a.w *= mul;
            *reinterpret_cast<float4*>(dbase + (size_t)t * (HK * DK)) = a;
        }
    } else {
        const int head = hb - 32;
        float* dbase = g_v + ((size_t)(b * S_LEN + t0) * HV + head) * DV + lane * 4;
#pragma unroll
        for (int t = 0; t < 16; t++) {
            float4 a;
            CONV_STEP(a, t);
            *reinterpret_cast<float4*>(dbase + (size_t)t * (HV * DV)) = a;
        }
    }
#undef CONV_STEP
}

// ---------------- kernel 1b: gating ----------------
__global__ __launch_bounds__(256) void gate_kernel(
    const float* __restrict__ bvec,
    const float* __restrict__ avec,
    const float* __restrict__ dt_bias,
    const float* __restrict__ alog)
{
    const int idx = blockIdx.x * 256 + threadIdx.x;
    const int h = idx & 31;
    float aa = avec[idx] + __ldg(dt_bias + h);
    float sp = (aa > 20.f) ? aa : log1pf(expf(aa));
    float g  = -expf(__ldg(alog + h)) * sp;
    float eg = expf(g);
    float bb = bvec[idx];
    float beta = 1.f / (1.f + expf(-bb));
    *reinterpret_cast<float2*>(g_gate + (size_t)idx * 2) = make_float2(eg, beta);
}

// ---------------- kernel 1c: group cross-scalars ----------------
// One warp per (b, hk, 4-token group): 12 dots among k1..k4, q1..q3.
__device__ __forceinline__ float dot4(float4 a, float4 b) {
    return a.x * b.x + a.y * b.y + a.z * b.z + a.w * b.w;
}
__global__ __launch_bounds__(256) void cross4_kernel()
{
    const int gw   = blockIdx.x * 8 + (threadIdx.x >> 5);   // 16384 warps
    const int lane = threadIdx.x & 31;
    const int b  = gw >> 13;
    const int hk = (gw >> 9) & 15;
    const int tg = gw & 511;

    const size_t base = ((size_t)(b * S_LEN + 4 * tg) * HK + hk) * DK + lane * 4;
    const float4 k1 = *reinterpret_cast<const float4*>(g_kn + base);
    const float4 k2 = *reinterpret_cast<const float4*>(g_kn + base + 1 * HK * DK);
    const float4 k3 = *reinterpret_cast<const float4*>(g_kn + base + 2 * HK * DK);
    const float4 k4 = *reinterpret_cast<const float4*>(g_kn + base + 3 * HK * DK);
    const float4 q1 = *reinterpret_cast<const float4*>(g_qn + base);
    const float4 q2 = *reinterpret_cast<const float4*>(g_qn + base + 1 * HK * DK);
    const float4 q3 = *reinterpret_cast<const float4*>(g_qn + base + 2 * HK * DK);

    float kk21 = dot4(k2, k1), kk31 = dot4(k3, k1), kk32 = dot4(k3, k2);
    float kk41 = dot4(k4, k1), kk42 = dot4(k4, k2), kk43 = dot4(k4, k3);
    float qk11 = dot4(q1, k1), qk21 = dot4(q2, k1), qk22 = dot4(q2, k2);
    float qk31 = dot4(q3, k1), qk32 = dot4(q3, k2), qk33 = dot4(q3, k3);
#pragma unroll
    for (int o = 16; o > 0; o >>= 1) {
        kk21 += __shfl_xor_sync(0xffffffffu, kk21, o);
        kk31 += __shfl_xor_sync(0xffffffffu, kk31, o);
        kk32 += __shfl_xor_sync(0xffffffffu, kk32, o);
        kk41 += __shfl_xor_sync(0xffffffffu, kk41, o);
        kk42 += __shfl_xor_sync(0xffffffffu, kk42, o);
        kk43 += __shfl_xor_sync(0xffffffffu, kk43, o);
        qk11 += __shfl_xor_sync(0xffffffffu, qk11, o);
        qk21 += __shfl_xor_sync(0xffffffffu, qk21, o);
        qk22 += __shfl_xor_sync(0xffffffffu, qk22, o);
        qk31 += __shfl_xor_sync(0xffffffffu, qk31, o);
        qk32 += __shfl_xor_sync(0xffffffffu, qk32, o);
        qk33 += __shfl_xor_sync(0xffffffffu, qk33, o);
    }
    if (lane == 0) {
        float4* dst = g_cross4 + ((size_t)(b * (S_LEN / 4) + tg) * HK + hk) * 3;
        dst[0] = make_float4(kk21, kk31, kk32, kk41);
        dst[1] = make_float4(kk42, kk43, qk11, qk21);
        dst[2] = make_float4(qk22, qk31, qk32, qk33);
    }
}

// ---------------- kernel 2: rank-4 (grouped-token) gated delta-rule ----------------
// grid 128 = (b, h, vh). 256 threads = 32 column-pairs x 8 k-slices of 16 dims.
// Per 4-token group: 7 dots on old state (k1..k4, q1..q3) + prev group's o4
// reduced in ONE interleaved shfl burst. u1..u4, o1..o3 via precomputed cross
// scalars. State updated once: S4 = e1234*S0 + sum ci*ki. o4 deferred.
__global__ __launch_bounds__(256, 1) void rec_kernel(float* __restrict__ out)
{
    const int blk = blockIdx.x;
    const int b   = blk >> 6;
    const int h   = (blk >> 1) & 31;
    const int vh  = blk & 1;
    const int hk  = h >> 1;

    const int tid = threadIdx.x;
    const int c2  = tid >> 3;          // column pair 0..31
    const int p   = tid & 7;           // k-slice 0..7 (16 dims)
    const bool lowp = (p < 4);

    __shared__ float sk[2][TB][8][20];
    __shared__ float sq[2][TB][8][20];
    __shared__ float sv[2][TB][64];
    __shared__ float2 sg[2][TB];
    __shared__ float4 scr[2][GB][3];

    ull so[8], sx[8];                  // owned / other column state
#pragma unroll
    for (int i = 0; i < 8; i++) { so[i] = 0ull; sx[i] = 0ull; }

    const float* kbase = g_kn + ((size_t)(b * S_LEN) * HK + hk) * DK;
    const float* qbase = g_qn + ((size_t)(b * S_LEN) * HK + hk) * DK;
    const float* vbase = g_v  + ((size_t)(b * S_LEN) * HV + h) * DV + vh * 64;
    const float* gbase = g_gate + ((size_t)(b * S_LEN) * HV + h) * 2;
    const size_t qk_stride = (size_t)HK * DK;
    const size_t v_stride  = (size_t)HV * DV;

    auto load_batch = [&](int buf, int t0) {
#pragma unroll
        for (int rep = 0; rep < 2; rep++) {
            int i  = tid + rep * 256;
            int tt = i >> 5, j = i & 31;
            cpa16(&sk[buf][tt][j >> 2][(j & 3) * 4],
                  kbase + (size_t)(t0 + tt) * qk_stride + j * 4);
            cpa16(&sq[buf][tt][j >> 2][(j & 3) * 4],
                  qbase + (size_t)(t0 + tt) * qk_stride + j * 4);
        }
        {
            int tt = tid >> 4, j = tid & 15;
            cpa16(&sv[buf][tt][j * 4],
                  vbase + (size_t)(t0 + tt) * v_stride + j * 4);
        }
        if (tid < TB)
            cpa8(&sg[buf][tid], gbase + (size_t)(t0 + tid) * (HV * 2));
        if (tid < GB * 3) {
            int g = tid / 3, part = tid % 3;
            cpa16(&scr[buf][g][part],
                  g_cross4 + ((size_t)(b * (S_LEN / 4) + (t0 >> 2) + g) * HK + hk) * 3 + part);
        }
        cpa_commit();
    };

    load_batch(0, 0);
    cpa_wait0();
    __syncthreads();
    int buf = 0;

    float* obase = out + ((size_t)(b * S_LEN) * HV + h) * DV + vh * 64 + c2 * 2;
    const int osel = lowp ? 0 : 1;

    float oo_m = 0.f, oo_o = 0.f;      // prev group's o4 partials (own/other)

#pragma unroll 1
    for (int t0 = 0; t0 < S_LEN; t0 += TB) {
        if (t0 + TB < S_LEN) load_batch(buf ^ 1, t0 + TB);

#pragma unroll 2
        for (int g = 0; g < GB; g++) {
            const int T = t0 + 4 * g;
            const int s0i = 4 * g;

            const float2 ga = sg[buf][s0i + 0];
            const float2 gb2 = sg[buf][s0i + 1];
            const float2 gc = sg[buf][s0i + 2];
            const float2 gd = sg[buf][s0i + 3];
            const float e1 = ga.x,  bb1 = ga.y;
            const float e2 = gb2.x, bb2 = gb2.y;
            const float e3 = gc.x,  bb3 = gc.y;
            const float e4 = gd.x,  bb4 = gd.y;
            const float4 cA = scr[buf][g][0];
            const float4 cB = scr[buf][g][1];
            const float4 cC = scr[buf][g][2];

            // ---- q dots on old state (q1..q3), slices die after this ----
            ull go1 = 0, go2 = 0, go3 = 0, gx1 = 0, gx2 = 0, gx3 = 0;
            {
                F4U qa[4], qb[4], qc[4];
                const float* q1p = &sq[buf][s0i + 0][p][0];
                const float* q2p = &sq[buf][s0i + 1][p][0];
                const float* q3p = &sq[buf][s0i + 2][p][0];
#pragma unroll
                for (int i = 0; i < 4; i++) {
                    qa[i].f = *reinterpret_cast<const float4*>(q1p + i * 4);
                    qb[i].f = *reinterpret_cast<const float4*>(q2p + i * 4);
                    qc[i].f = *reinterpret_cast<const float4*>(q3p + i * 4);
                }
#pragma unroll
                for (int i = 0; i < 4; i++) {
                    FMA2(go1, qa[i].u[0], so[2*i],   go1);
                    FMA2(go1, qa[i].u[1], so[2*i+1], go1);
                    FMA2(gx1, qa[i].u[0], sx[2*i],   gx1);
                    FMA2(gx1, qa[i].u[1], sx[2*i+1], gx1);
                    FMA2(go2, qb[i].u[0], so[2*i],   go2);
                    FMA2(go2, qb[i].u[1], so[2*i+1], go2);
                    FMA2(gx2, qb[i].u[0], sx[2*i],   gx2);
                    FMA2(gx2, qb[i].u[1], sx[2*i+1], gx2);
                    FMA2(go3, qc[i].u[0], so[2*i],   go3);
                    FMA2(go3, qc[i].u[1], so[2*i+1], go3);
                    FMA2(gx3, qc[i].u[0], sx[2*i],   gx3);
                    FMA2(gx3, qc[i].u[1], sx[2*i+1], gx3);
                }
            }

            // ---- k dots on old state (k1..k4 kept for the update) ----
            F4U k1[4], k2[4], k3[4], k4[4];
            {
                const float* k1p = &sk[buf][s0i + 0][p][0];
                const float* k2p = &sk[buf][s0i + 1][p][0];
                const float* k3p = &sk[buf][s0i + 2][p][0];
                const float* k4p = &sk[buf][s0i + 3][p][0];
#pragma unroll
                for (int i = 0; i < 4; i++) {
                    k1[i].f = *reinterpret_cast<const float4*>(k1p + i * 4);
                    k2[i].f = *reinterpret_cast<const float4*>(k2p + i * 4);
                    k3[i].f = *reinterpret_cast<const float4*>(k3p + i * 4);
                    k4[i].f = *reinterpret_cast<const float4*>(k4p + i * 4);
                }
            }
            ull ao1 = 0, ao2 = 0, ao3 = 0, ao4 = 0;
            ull ax1 = 0, ax2 = 0, ax3 = 0, ax4 = 0;
#pragma unroll
            for (int i = 0; i < 4; i++) {
                FMA2(ao1, k1[i].u[0], so[2*i],   ao1);
                FMA2(ao1, k1[i].u[1], so[2*i+1], ao1);
                FMA2(ax1, k1[i].u[0], sx[2*i],   ax1);
                FMA2(ax1, k1[i].u[1], sx[2*i+1], ax1);
                FMA2(ao2, k2[i].u[0], so[2*i],   ao2);
                FMA2(ao2, k2[i].u[1], so[2*i+1], ao2);
                FMA2(ax2, k2[i].u[0], sx[2*i],   ax2);
                FMA2(ax2, k2[i].u[1], sx[2*i+1], ax2);
                FMA2(ao3, k3[i].u[0], so[2*i],   ao3);
                FMA2(ao3, k3[i].u[1], so[2*i+1], ao3);
                FMA2(ax3, k3[i].u[0], sx[2*i],   ax3);
                FMA2(ax3, k3[i].u[1], sx[2*i+1], ax3);
                FMA2(ao4, k4[i].u[0], so[2*i],   ao4);
                FMA2(ao4, k4[i].u[1], so[2*i+1], ao4);
                FMA2(ax4, k4[i].u[0], sx[2*i],   ax4);
                FMA2(ax4, k4[i].u[1], sx[2*i+1], ax4);
            }

            float a1m = sum2(ao1), a2m = sum2(ao2), a3m = sum2(ao3), a4m = sum2(ao4);
            float g1m = sum2(go1), g2m = sum2(go2), g3m = sum2(go3);
            const float a1x = sum2(ax1), a2x = sum2(ax2), a3x = sum2(ax3), a4x = sum2(ax4);
            const float g1x = sum2(gx1), g2x = sum2(gx2), g3x = sum2(gx3);

            // ---- ONE interleaved burst: fold other-column, then 2 tree steps ----
            a1m += __shfl_xor_sync(0xffffffffu, a1x, 4);
            a2m += __shfl_xor_sync(0xffffffffu, a2x, 4);
            a3m += __shfl_xor_sync(0xffffffffu, a3x, 4);
            a4m += __shfl_xor_sync(0xffffffffu, a4x, 4);
            g1m += __shfl_xor_sync(0xffffffffu, g1x, 4);
            g2m += __shfl_xor_sync(0xffffffffu, g2x, 4);
            g3m += __shfl_xor_sync(0xffffffffu, g3x, 4);
            oo_m += __shfl_xor_sync(0xffffffffu, oo_o, 4);
#pragma unroll
            for (int o = 1; o <= 2; o <<= 1) {
                a1m += __shfl_xor_sync(0xffffffffu, a1m, o);
                a2m += __shfl_xor_sync(0xffffffffu, a2m, o);
                a3m += __shfl_xor_sync(0xffffffffu, a3m, o);
                a4m += __shfl_xor_sync(0xffffffffu, a4m, o);
                g1m += __shfl_xor_sync(0xffffffffu, g1m, o);
                g2m += __shfl_xor_sync(0xffffffffu, g2m, o);
                g3m += __shfl_xor_sync(0xffffffffu, g3m, o);
                oo_m += __shfl_xor_sync(0xffffffffu, oo_m, o);
            }

            // prev group's o4 store (deferred)
            if (T != 0 && (p & 3) == 0)
                obase[(size_t)(T - 1) * v_stride + osel] = oo_m;

            // ---- scalar chain ----
            const float2 v1f = *reinterpret_cast<const float2*>(&sv[buf][s0i + 0][c2 * 2]);
            const float2 v2f = *reinterpret_cast<const float2*>(&sv[buf][s0i + 1][c2 * 2]);
            const float2 v3f = *reinterpret_cast<const float2*>(&sv[buf][s0i + 2][c2 * 2]);
            const float2 v4f = *reinterpret_cast<const float2*>(&sv[buf][s0i + 3][c2 * 2]);
            const float v1o = lowp ? v1f.x : v1f.y;
            const float v2o = lowp ? v2f.x : v2f.y;
            const float v3o = lowp ? v3f.x : v3f.y;
            const float v4o = lowp ? v4f.x : v4f.y;

            const float e12 = e1 * e2, e23 = e2 * e3, e34 = e3 * e4;
            const float e123 = e12 * e3, e234 = e23 * e4, e1234 = e12 * e34;

            const float u1 = bb1 * (v1o - e1 * a1m);
            const float u2 = bb2 * (v2o - e2 * (e1 * a2m + cA.x * u1));
            const float u3 = bb3 * (v3o - e3 * (e12 * a3m + e2 * cA.y * u1 + cA.z * u2));
            const float u4 = bb4 * (v4o - e4 * (e123 * a4m + e23 * cA.w * u1
                                                + e3 * cB.x * u2 + cB.y * u3));
            const float o1 = e1 * g1m + cB.z * u1;
            const float o2 = e12 * g2m + e2 * cB.w * u1 + cC.x * u2;
            const float o3 = e123 * g3m + e23 * cC.y * u1 + e3 * cC.z * u2 + cC.w * u3;
            if ((p & 3) == 0) {
                obase[(size_t)(T + 0) * v_stride + osel] = o1;
                obase[(size_t)(T + 1) * v_stride + osel] = o2;
                obase[(size_t)(T + 2) * v_stride + osel] = o3;
            }

            // ---- state update: S4 = e1234*S0 + c1*k1 + c2*k2 + c3*k3 + c4*k4 ----
            const float c1 = e234 * u1, c2s = e34 * u2, c3s = e4 * u3, c4s = u4;
            const float c1x = __shfl_xor_sync(0xffffffffu, c1, 4);
            const float c2x = __shfl_xor_sync(0xffffffffu, c2s, 4);
            const float c3x = __shfl_xor_sync(0xffffffffu, c3s, 4);
            const float c4x = __shfl_xor_sync(0xffffffffu, c4s, 4);

            const ull ep  = pack2(e1234, e1234);
            const ull c1p = pack2(c1, c1), c2p = pack2(c2s, c2s);
            const ull c3p = pack2(c3s, c3s), c4p = pack2(c4s, c4s);
#pragma unroll
            for (int i = 0; i < 4; i++) {      // owned update: overlaps exchange
                MUL2(so[2*i],   so[2*i],   ep);
                MUL2(so[2*i+1], so[2*i+1], ep);
                FMA2(so[2*i],   k1[i].u[0], c1p, so[2*i]);
                FMA2(so[2*i+1], k1[i].u[1], c1p, so[2*i+1]);
                FMA2(so[2*i],   k2[i].u[0], c2p, so[2*i]);
                FMA2(so[2*i+1], k2[i].u[1], c2p, so[2*i+1]);
                FMA2(so[2*i],   k3[i].u[0], c3p, so[2*i]);
                FMA2(so[2*i+1], k3[i].u[1], c3p, so[2*i+1]);
                FMA2(so[2*i],   k4[i].u[0], c4p, so[2*i]);
                FMA2(so[2*i+1], k4[i].u[1], c4p, so[2*i+1]);
            }
            const ull c1xp = pack2(c1x, c1x), c2xp = pack2(c2x, c2x);
            const ull c3xp = pack2(c3x, c3x), c4xp = pack2(c4x, c4x);
#pragma unroll
            for (int i = 0; i < 4; i++) {
                MUL2(sx[2*i],   sx[2*i],   ep);
                MUL2(sx[2*i+1], sx[2*i+1], ep);
                FMA2(sx[2*i],   k1[i].u[0], c1xp, sx[2*i]);
                FMA2(sx[2*i+1], k1[i].u[1], c1xp, sx[2*i+1]);
                FMA2(sx[2*i],   k2[i].u[0], c2xp, sx[2*i]);
                FMA2(sx[2*i+1], k2[i].u[1], c2xp, sx[2*i+1]);
                FMA2(sx[2*i],   k3[i].u[0], c3xp, sx[2*i]);
                FMA2(sx[2*i+1], k3[i].u[1], c3xp, sx[2*i+1]);
                FMA2(sx[2*i],   k4[i].u[0], c4xp, sx[2*i]);
                FMA2(sx[2*i+1], k4[i].u[1], c4xp, sx[2*i+1]);
            }

            // ---- deferred o4 partials: q4 . S4 ----
            {
                F4U q4[4];
                const float* q4p = &sq[buf][s0i + 3][p][0];
#pragma unroll
                for (int i = 0; i < 4; i++)
                    q4[i].f = *reinterpret_cast<const float4*>(q4p + i * 4);
                ull qo0 = 0, qo1 = 0, qx0 = 0, qx1 = 0;
#pragma unroll
                for (int i = 0; i < 4; i++) {
                    FMA2(qo0, q4[i].u[0], so[2*i],   qo0);
                    FMA2(qo1, q4[i].u[1], so[2*i+1], qo1);
                    FMA2(qx0, q4[i].u[0], sx[2*i],   qx0);
                    FMA2(qx1, q4[i].u[1], sx[2*i+1], qx1);
                }
                ADD2(qo0, qo0, qo1);
                ADD2(qx0, qx0, qx1);
                oo_m = sum2(qo0);
                oo_o = sum2(qx0);
            }
        }

        cpa_wait0();
        __syncthreads();
        buf ^= 1;
    }

    // drain: reduce and store the final token's o4
    {
        oo_m += __shfl_xor_sync(0xffffffffu, oo_o, 4);
        oo_m += __shfl_xor_sync(0xffffffffu, oo_m, 1);
        oo_m += __shfl_xor_sync(0xffffffffu, oo_m, 2);
        if ((p & 3) == 0)
            obase[(size_t)(S_LEN - 1) * v_stride + osel] = oo_m;
    }
}

// ---------------- launch ----------------
extern "C" void kernel_launch(void* const* d_in, const int* in_sizes, int n_in,
                              void* d_out, int out_size)
{
    const float* mixed_qkv = (const float*)d_in[0];
    const float* bvec      = (const float*)d_in[1];
    const float* avec      = (const float*)d_in[2];
    const float* convw     = (const float*)d_in[3];
    const float* dt_bias   = (const float*)d_in[4];
    const float* alog      = (const float*)d_in[5];
    float* out = (float*)d_out;

    prep_kernel<<<2048, 256>>>(mixed_qkv, convw);
    cross4_kernel<<<BQ * HK * (S_LEN / 4) / 8, 256>>>();
    gate_kernel<<<NROWS * HV / 256, 256>>>(bvec, avec, dt_bias, alog);
    rec_kernel<<<BQ * HV * 2, 256>>>(out);
}